// round 6
// baseline (speedup 1.0000x reference)
#include <cuda_runtime.h>
#include <math.h>

#define BB 64
#define PP 512
#define NN 512
#define EE 128
#define FFD 512
#define LLAYERS 6
#define M_TOT (BB*NN)
#define EPS 1e-5f
#define INV_SQRT_E 0.08838834764831845f  /* 1/sqrt(128) */

typedef unsigned long long u64;

__device__ __forceinline__ u64 pk2(float x, float y) {
    u64 r; asm("mov.b64 %0,{%1,%2};" : "=l"(r) : "f"(x), "f"(y)); return r;
}
__device__ __forceinline__ void fma2(u64& d, u64 a, u64 b) {
    asm("fma.rn.f32x2 %0,%1,%2,%0;" : "+l"(d) : "l"(a), "l"(b));
}
__device__ __forceinline__ float2 up2(u64 v) {
    float lo, hi; asm("mov.b64 {%0,%1},%2;" : "=f"(lo), "=f"(hi) : "l"(v));
    float2 f; f.x = lo; f.y = hi; return f;
}

// ---------------- scratch (static device globals; no alloc allowed) ----------------
__device__ float g_x  [BB*NN*EE];
__device__ float g_y  [BB*NN*EE];
__device__ float g_h  [BB*NN*EE];
__device__ float g_sq [BB*NN*EE];
__device__ float g_ek [BB*NN*EE];
__device__ float g_ekv[BB*NN*EE];
__device__ float g_hid[BB*NN*FFD];
__device__ float g_aft[BB*PP*EE];
__device__ float g_gq [BB*EE];
__device__ float g_gm [BB*EE];

// ---------------- embedding ----------------
__global__ void embed_kernel(const float* __restrict__ data,
                             const float* __restrict__ W,
                             const float* __restrict__ bias,
                             float* __restrict__ X) {
    int idx = blockIdx.x;
    int e   = threadIdx.x;
    float d0 = data[idx*2+0], d1 = data[idx*2+1];
    X[(size_t)idx*EE + e] = d0*W[e] + d1*W[EE+e] + bias[e];
}

// ---------------- qkv GEMM (triple accumulator, f32x2) ----------------
__global__ __launch_bounds__(256) void qkv_kernel(
        const float* __restrict__ X,
        const float* __restrict__ Wq,
        const float* __restrict__ Wk,
        const float* __restrict__ Wv,
        float* __restrict__ SQ,
        float* __restrict__ EK,
        float* __restrict__ EKV) {
    const int m0 = blockIdx.x*64, n0 = blockIdx.y*64;
    __shared__ float As[16][64];
    __shared__ float Bq[16][64], Bk[16][64], Bv[16][64];
    u64 aq[4][2] = {}, ak[4][2] = {}, av[4][2] = {};
    int tid = threadIdx.x, tx = tid & 15, ty = tid >> 4;

    for (int k0 = 0; k0 < EE; k0 += 16) {
        #pragma unroll
        for (int i = 0; i < 4; i++) {
            int e = tid + i*256; int m = e >> 4, k = e & 15;
            As[k][m] = X[(size_t)(m0+m)*EE + k0 + k];
        }
        #pragma unroll
        for (int i = 0; i < 4; i++) {
            int e = tid + i*256; int k = e >> 6, n = e & 63;
            Bq[k][n] = Wq[(k0+k)*EE + n0 + n];
            Bk[k][n] = Wk[(k0+k)*EE + n0 + n];
            Bv[k][n] = Wv[(k0+k)*EE + n0 + n];
        }
        __syncthreads();
        #pragma unroll
        for (int kk = 0; kk < 16; kk++) {
            float4 a4 = *(const float4*)&As[kk][ty*4];
            u64 ap[4] = {pk2(a4.x,a4.x), pk2(a4.y,a4.y), pk2(a4.z,a4.z), pk2(a4.w,a4.w)};
            ulonglong2 qb = *(const ulonglong2*)&Bq[kk][tx*4];
            ulonglong2 kb = *(const ulonglong2*)&Bk[kk][tx*4];
            ulonglong2 vb = *(const ulonglong2*)&Bv[kk][tx*4];
            #pragma unroll
            for (int i = 0; i < 4; i++) {
                fma2(aq[i][0], ap[i], qb.x); fma2(aq[i][1], ap[i], qb.y);
                fma2(ak[i][0], ap[i], kb.x); fma2(ak[i][1], ap[i], kb.y);
                fma2(av[i][0], ap[i], vb.x); fma2(av[i][1], ap[i], vb.y);
            }
        }
        __syncthreads();
    }
    #pragma unroll
    for (int i = 0; i < 4; i++) {
        float2 q0 = up2(aq[i][0]), q1 = up2(aq[i][1]);
        float2 k0v = up2(ak[i][0]), k1v = up2(ak[i][1]);
        float2 v0 = up2(av[i][0]), v1 = up2(av[i][1]);
        float qv[4] = {q0.x, q0.y, q1.x, q1.y};
        float kv[4] = {k0v.x, k0v.y, k1v.x, k1v.y};
        float vv[4] = {v0.x, v0.y, v1.x, v1.y};
        #pragma unroll
        for (int j = 0; j < 4; j++) {
            int row = m0 + ty*4 + i, col = n0 + tx*4 + j;
            size_t o = (size_t)row*EE + col;
            SQ[o] = 1.f/(1.f + __expf(-qv[j]));
            float ekk = __expf(kv[j]);
            EK[o]  = ekk;
            EKV[o] = ekk*vv[j];
        }
    }
}

// ---------------- dec k/v GEMM (dual accumulator, f32x2) ----------------
__global__ __launch_bounds__(256) void deckv_kernel(
        const float* __restrict__ X,
        const float* __restrict__ Wk,
        const float* __restrict__ Wv,
        float* __restrict__ EK,
        float* __restrict__ EKV) {
    const int m0 = blockIdx.x*64, n0 = blockIdx.y*64;
    __shared__ float As[16][64];
    __shared__ float Bk[16][64], Bv[16][64];
    u64 ak[4][2] = {}, av[4][2] = {};
    int tid = threadIdx.x, tx = tid & 15, ty = tid >> 4;

    for (int k0 = 0; k0 < EE; k0 += 16) {
        #pragma unroll
        for (int i = 0; i < 4; i++) {
            int e = tid + i*256; int m = e >> 4, k = e & 15;
            As[k][m] = X[(size_t)(m0+m)*EE + k0 + k];
        }
        #pragma unroll
        for (int i = 0; i < 4; i++) {
            int e = tid + i*256; int k = e >> 6, n = e & 63;
            Bk[k][n] = Wk[(k0+k)*EE + n0 + n];
            Bv[k][n] = Wv[(k0+k)*EE + n0 + n];
        }
        __syncthreads();
        #pragma unroll
        for (int kk = 0; kk < 16; kk++) {
            float4 a4 = *(const float4*)&As[kk][ty*4];
            u64 ap[4] = {pk2(a4.x,a4.x), pk2(a4.y,a4.y), pk2(a4.z,a4.z), pk2(a4.w,a4.w)};
            ulonglong2 kb = *(const ulonglong2*)&Bk[kk][tx*4];
            ulonglong2 vb = *(const ulonglong2*)&Bv[kk][tx*4];
            #pragma unroll
            for (int i = 0; i < 4; i++) {
                fma2(ak[i][0], ap[i], kb.x); fma2(ak[i][1], ap[i], kb.y);
                fma2(av[i][0], ap[i], vb.x); fma2(av[i][1], ap[i], vb.y);
            }
        }
        __syncthreads();
    }
    #pragma unroll
    for (int i = 0; i < 4; i++) {
        float2 k0v = up2(ak[i][0]), k1v = up2(ak[i][1]);
        float2 v0 = up2(av[i][0]), v1 = up2(av[i][1]);
        float kv[4] = {k0v.x, k0v.y, k1v.x, k1v.y};
        float vv[4] = {v0.x, v0.y, v1.x, v1.y};
        #pragma unroll
        for (int j = 0; j < 4; j++) {
            int row = m0 + ty*4 + i, col = n0 + tx*4 + j;
            size_t o = (size_t)row*EE + col;
            float ekk = __expf(kv[j]);
            EK[o]  = ekk;
            EKV[o] = ekk*vv[j];
        }
    }
}

// ---------------- encoder AFT: 64x128 tile, dual GEMM, f32x2 ----------------
__global__ __launch_bounds__(256) void aft_enc_kernel(
        const float* __restrict__ dist,
        const float* __restrict__ ls,
        const float* __restrict__ alpha, int l,
        const float* __restrict__ EKV,
        const float* __restrict__ EK,
        const float* __restrict__ X,
        const float* __restrict__ SQ,
        float* __restrict__ Y) {
    int b = blockIdx.z;
    const int m0 = blockIdx.x*64;
    float s = ls[0]*alpha[l];
    const float* D  = dist + (size_t)b*NN*NN;
    const float* B1 = EKV  + (size_t)b*NN*EE;
    const float* B2 = EK   + (size_t)b*NN*EE;
    __shared__ float As[16][64], Bs1[16][128], Bs2[16][128];
    u64 a1[4][4] = {}, a2[4][4] = {};
    int tid = threadIdx.x, tx = tid & 15, ty = tid >> 4;
    int br = tid >> 4, bc = (tid & 15)*8;

    for (int k0 = 0; k0 < NN; k0 += 16) {
        #pragma unroll
        for (int i = 0; i < 4; i++) {
            int e = tid + i*256; int m = e >> 4, k = e & 15;
            As[k][m] = __expf(s * D[(size_t)(m0+m)*NN + k0 + k]);
        }
        {
            size_t go = (size_t)(k0+br)*EE + bc;
            *(float4*)&Bs1[br][bc]   = *(const float4*)&B1[go];
            *(float4*)&Bs1[br][bc+4] = *(const float4*)&B1[go+4];
            *(float4*)&Bs2[br][bc]   = *(const float4*)&B2[go];
            *(float4*)&Bs2[br][bc+4] = *(const float4*)&B2[go+4];
        }
        __syncthreads();
        #pragma unroll
        for (int kk = 0; kk < 16; kk++) {
            float4 a4 = *(const float4*)&As[kk][ty*4];
            u64 ap[4] = {pk2(a4.x,a4.x), pk2(a4.y,a4.y), pk2(a4.z,a4.z), pk2(a4.w,a4.w)};
            ulonglong2 p0 = *(const ulonglong2*)&Bs1[kk][tx*8];
            ulonglong2 p1 = *(const ulonglong2*)&Bs1[kk][tx*8+4];
            ulonglong2 q0 = *(const ulonglong2*)&Bs2[kk][tx*8];
            ulonglong2 q1 = *(const ulonglong2*)&Bs2[kk][tx*8+4];
            u64 b1p[4] = {p0.x, p0.y, p1.x, p1.y};
            u64 b2p[4] = {q0.x, q0.y, q1.x, q1.y};
            #pragma unroll
            for (int i = 0; i < 4; i++)
                #pragma unroll
                for (int p = 0; p < 4; p++) {
                    fma2(a1[i][p], ap[i], b1p[p]);
                    fma2(a2[i][p], ap[i], b2p[p]);
                }
        }
        __syncthreads();
    }
    #pragma unroll
    for (int i = 0; i < 4; i++) {
        int row = m0 + ty*4 + i;
        size_t base = ((size_t)b*NN + row)*EE + tx*8;
        float4 x0 = *(const float4*)&X[base],  x1 = *(const float4*)&X[base+4];
        float4 s0 = *(const float4*)&SQ[base], s1 = *(const float4*)&SQ[base+4];
        float2 n0v = up2(a1[i][0]), n1v = up2(a1[i][1]), n2v = up2(a1[i][2]), n3v = up2(a1[i][3]);
        float2 d0v = up2(a2[i][0]), d1v = up2(a2[i][1]), d2v = up2(a2[i][2]), d3v = up2(a2[i][3]);
        float4 o0, o1;
        o0.x = x0.x + s0.x*(n0v.x/d0v.x);
        o0.y = x0.y + s0.y*(n0v.y/d0v.y);
        o0.z = x0.z + s0.z*(n1v.x/d1v.x);
        o0.w = x0.w + s0.w*(n1v.y/d1v.y);
        o1.x = x1.x + s1.x*(n2v.x/d2v.x);
        o1.y = x1.y + s1.y*(n2v.y/d2v.y);
        o1.z = x1.z + s1.z*(n3v.x/d3v.x);
        o1.w = x1.w + s1.w*(n3v.y/d3v.y);
        *(float4*)&Y[base]   = o0;
        *(float4*)&Y[base+4] = o1;
    }
}

// ---------------- decoder AFT: 64x128 tile, f32x2 ----------------
__global__ __launch_bounds__(256) void dec_aft_kernel(
        const float* __restrict__ cur_dist,
        const float* __restrict__ ninf,
        const float* __restrict__ ls,
        const float* __restrict__ dalpha,
        const float* __restrict__ EKV,
        const float* __restrict__ EK,
        const float* __restrict__ GQ,
        const float* __restrict__ cap,
        const float* __restrict__ dWq,
        float* __restrict__ AFT) {
    int b = blockIdx.z;
    const int m0 = blockIdx.x*64;
    float s = ls[0]*dalpha[0];
    const float* CD = cur_dist + (size_t)b*PP*NN;
    const float* NM = ninf     + (size_t)b*PP*NN;
    const float* B1 = EKV + (size_t)b*NN*EE;
    const float* B2 = EK  + (size_t)b*NN*EE;
    __shared__ float As[16][64], Bs1[16][128], Bs2[16][128];
    u64 a1[4][4] = {}, a2[4][4] = {};
    int tid = threadIdx.x, tx = tid & 15, ty = tid >> 4;
    int br = tid >> 4, bc = (tid & 15)*8;

    for (int k0 = 0; k0 < NN; k0 += 16) {
        #pragma unroll
        for (int i = 0; i < 4; i++) {
            int e = tid + i*256; int m = e >> 4, k = e & 15;
            size_t off = (size_t)(m0+m)*NN + k0 + k;
            As[k][m] = __expf(s*CD[off] + NM[off]);
        }
        {
            size_t go = (size_t)(k0+br)*EE + bc;
            *(float4*)&Bs1[br][bc]   = *(const float4*)&B1[go];
            *(float4*)&Bs1[br][bc+4] = *(const float4*)&B1[go+4];
            *(float4*)&Bs2[br][bc]   = *(const float4*)&B2[go];
            *(float4*)&Bs2[br][bc+4] = *(const float4*)&B2[go+4];
        }
        __syncthreads();
        #pragma unroll
        for (int kk = 0; kk < 16; kk++) {
            float4 a4 = *(const float4*)&As[kk][ty*4];
            u64 ap[4] = {pk2(a4.x,a4.x), pk2(a4.y,a4.y), pk2(a4.z,a4.z), pk2(a4.w,a4.w)};
            ulonglong2 p0 = *(const ulonglong2*)&Bs1[kk][tx*8];
            ulonglong2 p1 = *(const ulonglong2*)&Bs1[kk][tx*8+4];
            ulonglong2 q0 = *(const ulonglong2*)&Bs2[kk][tx*8];
            ulonglong2 q1 = *(const ulonglong2*)&Bs2[kk][tx*8+4];
            u64 b1p[4] = {p0.x, p0.y, p1.x, p1.y};
            u64 b2p[4] = {q0.x, q0.y, q1.x, q1.y};
            #pragma unroll
            for (int i = 0; i < 4; i++)
                #pragma unroll
                for (int p = 0; p < 4; p++) {
                    fma2(a1[i][p], ap[i], b1p[p]);
                    fma2(a2[i][p], ap[i], b2p[p]);
                }
        }
        __syncthreads();
    }
    #pragma unroll
    for (int i = 0; i < 4; i++) {
        int p = m0 + ty*4 + i;
        float cv = cap[(size_t)b*PP + p];
        int e0 = tx*8;
        float2 n0v = up2(a1[i][0]), n1v = up2(a1[i][1]), n2v = up2(a1[i][2]), n3v = up2(a1[i][3]);
        float2 d0v = up2(a2[i][0]), d1v = up2(a2[i][1]), d2v = up2(a2[i][2]), d3v = up2(a2[i][3]);
        float num[8] = {n0v.x, n0v.y, n1v.x, n1v.y, n2v.x, n2v.y, n3v.x, n3v.y};
        float den[8] = {d0v.x, d0v.y, d1v.x, d1v.y, d2v.x, d2v.y, d3v.x, d3v.y};
        float4 g0 = *(const float4*)&GQ[b*EE + e0], g1 = *(const float4*)&GQ[b*EE + e0 + 4];
        float4 w0 = *(const float4*)&dWq[EE*EE + e0], w1 = *(const float4*)&dWq[EE*EE + e0 + 4];
        float gq8[8] = {g0.x,g0.y,g0.z,g0.w,g1.x,g1.y,g1.z,g1.w};
        float wq8[8] = {w0.x,w0.y,w0.z,w0.w,w1.x,w1.y,w1.z,w1.w};
        float out[8];
        #pragma unroll
        for (int j = 0; j < 8; j++) {
            float qv = gq8[j] + cv*wq8[j];
            float sg = 1.f/(1.f + __expf(-qv));
            out[j] = sg*(num[j]/den[j]);
        }
        size_t base = ((size_t)b*PP + p)*EE + e0;
        *(float4*)&AFT[base]   = make_float4(out[0], out[1], out[2], out[3]);
        *(float4*)&AFT[base+4] = make_float4(out[4], out[5], out[6], out[7]);
    }
}

// ---------------- FF1: hid = relu(h@W1 + b1), f32x2 ----------------
__global__ __launch_bounds__(256) void ff1_kernel(
        const float* __restrict__ H,
        const float* __restrict__ W1,
        const float* __restrict__ b1,
        float* __restrict__ HID) {
    const int m0 = blockIdx.x*64, n0 = blockIdx.y*64;
    __shared__ float As[16][64], Bs[16][64];
    u64 acc[4][2] = {};
    int tid = threadIdx.x, tx = tid & 15, ty = tid >> 4;
    for (int k0 = 0; k0 < EE; k0 += 16) {
        #pragma unroll
        for (int i = 0; i < 4; i++) {
            int e = tid + i*256; int m = e >> 4, k = e & 15;
            As[k][m] = H[(size_t)(m0+m)*EE + k0 + k];
        }
        #pragma unroll
        for (int i = 0; i < 4; i++) {
            int e = tid + i*256; int k = e >> 6, n = e & 63;
            Bs[k][n] = W1[(k0+k)*FFD + n0 + n];
        }
        __syncthreads();
        #pragma unroll
        for (int kk = 0; kk < 16; kk++) {
            float4 a4 = *(const float4*)&As[kk][ty*4];
            u64 ap[4] = {pk2(a4.x,a4.x), pk2(a4.y,a4.y), pk2(a4.z,a4.z), pk2(a4.w,a4.w)};
            ulonglong2 bb = *(const ulonglong2*)&Bs[kk][tx*4];
            #pragma unroll
            for (int i = 0; i < 4; i++) {
                fma2(acc[i][0], ap[i], bb.x);
                fma2(acc[i][1], ap[i], bb.y);
            }
        }
        __syncthreads();
    }
    #pragma unroll
    for (int i = 0; i < 4; i++) {
        float2 c0 = up2(acc[i][0]), c1 = up2(acc[i][1]);
        float cv[4] = {c0.x, c0.y, c1.x, c1.y};
        #pragma unroll
        for (int j = 0; j < 4; j++) {
            int row = m0 + ty*4 + i, col = n0 + tx*4 + j;
            HID[(size_t)row*FFD + col] = fmaxf(cv[j] + b1[col], 0.f);
        }
    }
}

// ---------------- FF2: y = h + hid@W2 + b2, f32x2 ----------------
__global__ __launch_bounds__(256) void ff2_kernel(
        const float* __restrict__ HID,
        const float* __restrict__ W2,
        const float* __restrict__ b2,
        const float* __restrict__ H,
        float* __restrict__ Y) {
    const int m0 = blockIdx.x*64, n0 = blockIdx.y*64;
    __shared__ float As[16][64], Bs[16][64];
    u64 acc[4][2] = {};
    int tid = threadIdx.x, tx = tid & 15, ty = tid >> 4;
    for (int k0 = 0; k0 < FFD; k0 += 16) {
        #pragma unroll
        for (int i = 0; i < 4; i++) {
            int e = tid + i*256; int m = e >> 4, k = e & 15;
            As[k][m] = HID[(size_t)(m0+m)*FFD + k0 + k];
        }
        #pragma unroll
        for (int i = 0; i < 4; i++) {
            int e = tid + i*256; int k = e >> 6, n = e & 63;
            Bs[k][n] = W2[(k0+k)*EE + n0 + n];
        }
        __syncthreads();
        #pragma unroll
        for (int kk = 0; kk < 16; kk++) {
            float4 a4 = *(const float4*)&As[kk][ty*4];
            u64 ap[4] = {pk2(a4.x,a4.x), pk2(a4.y,a4.y), pk2(a4.z,a4.z), pk2(a4.w,a4.w)};
            ulonglong2 bb = *(const ulonglong2*)&Bs[kk][tx*4];
            #pragma unroll
            for (int i = 0; i < 4; i++) {
                fma2(acc[i][0], ap[i], bb.x);
                fma2(acc[i][1], ap[i], bb.y);
            }
        }
        __syncthreads();
    }
    #pragma unroll
    for (int i = 0; i < 4; i++) {
        float2 c0 = up2(acc[i][0]), c1 = up2(acc[i][1]);
        float cv[4] = {c0.x, c0.y, c1.x, c1.y};
        #pragma unroll
        for (int j = 0; j < 4; j++) {
            int row = m0 + ty*4 + i, col = n0 + tx*4 + j;
            size_t o = (size_t)row*EE + col;
            Y[o] = H[o] + cv[j] + b2[col];
        }
    }
}

// ---------------- instance norm over node dim (axis=1) ----------------
__global__ void inorm_kernel(const float* __restrict__ src,
                             float* __restrict__ dst,
                             const float* __restrict__ w,
                             const float* __restrict__ bias) {
    int b = blockIdx.x;
    int e = threadIdx.x;
    int c = threadIdx.y;
    const float* S = src + (size_t)b*NN*EE;
    float s = 0.f, s2 = 0.f;
    for (int n = c*64; n < c*64 + 64; n++) {
        float v = S[(size_t)n*EE + e];
        s += v; s2 += v*v;
    }
    __shared__ float ssum[8][128], ssq[8][128];
    __shared__ float smu[128], srs[128];
    ssum[c][e] = s; ssq[c][e] = s2;
    __syncthreads();
    if (c == 0) {
        float ts = 0.f, t2 = 0.f;
        #pragma unroll
        for (int i = 0; i < 8; i++) { ts += ssum[i][e]; t2 += ssq[i][e]; }
        float mu = ts*(1.f/NN);
        float var = t2*(1.f/NN) - mu*mu;
        smu[e] = mu;
        srs[e] = rsqrtf(var + EPS);
    }
    __syncthreads();
    float mu = smu[e], rs = srs[e], ww = w[e], bb = bias[e];
    float* Dd = dst + (size_t)b*NN*EE;
    for (int n = c*64; n < c*64 + 64; n++) {
        size_t o = (size_t)n*EE + e;
        Dd[o] = (S[o] - mu)*rs*ww + bb;
    }
}

// ---------------- graph mean over nodes ----------------
__global__ void gmean_kernel(const float* __restrict__ X, float* __restrict__ GM) {
    int b = blockIdx.x, e = threadIdx.x, c = threadIdx.y;
    float s = 0.f;
    for (int n = c*64; n < c*64 + 64; n++)
        s += X[((size_t)b*NN + n)*EE + e];
    __shared__ float sm[8][128];
    sm[c][e] = s;
    __syncthreads();
    if (c == 0) {
        float t = 0.f;
        #pragma unroll
        for (int i = 0; i < 8; i++) t += sm[i][e];
        GM[b*EE + e] = t*(1.f/NN);
    }
}

// ---------------- gq = gmean @ dWq[0:E,:] ----------------
__global__ void gq_kernel(const float* __restrict__ GM,
                          const float* __restrict__ dWq,
                          float* __restrict__ GQ) {
    int b = blockIdx.x, e = threadIdx.x;
    float acc = 0.f;
    for (int i = 0; i < EE; i++)
        acc += GM[b*EE + i]*dWq[i*EE + e];
    GQ[b*EE + e] = acc;
}

// ---------------- score GEMM: S = aft @ enc^T (NT) + epilogue, f32x2 ----------------
__global__ __launch_bounds__(256) void score_kernel(
        const float* __restrict__ AFT,
        const float* __restrict__ ENC,
        const float* __restrict__ cur_dist,
        const float* __restrict__ ninf,
        const float* __restrict__ ls,
        const float* __restrict__ palpha,
        float* __restrict__ OUT) {
    int b = blockIdx.z;
    const int p0 = blockIdx.x*64, n0 = blockIdx.y*64;
    float ps = ls[0]*palpha[0];
    const float* A = AFT + (size_t)b*PP*EE;
    const float* Eb = ENC + (size_t)b*NN*EE;
    __shared__ float As[16][64], Bs[16][64];
    u64 acc[4][2] = {};
    int tid = threadIdx.x, tx = tid & 15, ty = tid >> 4;
    for (int k0 = 0; k0 < EE; k0 += 16) {
        #pragma unroll
        for (int i = 0; i < 4; i++) {
            int e = tid + i*256; int m = e >> 4, k = e & 15;
            As[k][m] = A[(size_t)(p0+m)*EE + k0 + k];
        }
        #pragma unroll
        for (int i = 0; i < 4; i++) {
            int e = tid + i*256; int kk = e & 15, nn = e >> 4;
            Bs[kk][nn] = Eb[(size_t)(n0+nn)*EE + k0 + kk];
        }
        __syncthreads();
        #pragma unroll
        for (int kk = 0; kk < 16; kk++) {
            float4 a4 = *(const float4*)&As[kk][ty*4];
            u64 ap[4] = {pk2(a4.x,a4.x), pk2(a4.y,a4.y), pk2(a4.z,a4.z), pk2(a4.w,a4.w)};
            ulonglong2 bb = *(const ulonglong2*)&Bs[kk][tx*4];
            #pragma unroll
            for (int i = 0; i < 4; i++) {
                fma2(acc[i][0], ap[i], bb.x);
                fma2(acc[i][1], ap[i], bb.y);
            }
        }
        __syncthreads();
    }
    #pragma unroll
    for (int i = 0; i < 4; i++) {
        float2 c0 = up2(acc[i][0]), c1 = up2(acc[i][1]);
        float cv[4] = {c0.x, c0.y, c1.x, c1.y};
        #pragma unroll
        for (int j = 0; j < 4; j++) {
            int p = p0 + ty*4 + i, n = n0 + tx*4 + j;
            size_t o = ((size_t)b*PP + p)*NN + n;
            float sc = cv[j]*INV_SQRT_E + ps*cur_dist[o];
            OUT[o] = 10.f*tanhf(sc) + ninf[o];
        }
    }
}

// ---------------- row softmax over last dim (512) ----------------
__global__ void softmax_kernel(float* __restrict__ OUT) {
    float* row = OUT + (size_t)blockIdx.x*NN;
    int t = threadIdx.x;
    float v[4];
    #pragma unroll
    for (int i = 0; i < 4; i++) v[i] = row[t + i*128];
    float m = fmaxf(fmaxf(v[0], v[1]), fmaxf(v[2], v[3]));
    __shared__ float red[4];
    #pragma unroll
    for (int off = 16; off > 0; off >>= 1)
        m = fmaxf(m, __shfl_xor_sync(0xffffffff, m, off));
    if ((t & 31) == 0) red[t >> 5] = m;
    __syncthreads();
    m = fmaxf(fmaxf(red[0], red[1]), fmaxf(red[2], red[3]));
    __syncthreads();
    float s = 0.f;
    #pragma unroll
    for (int i = 0; i < 4; i++) { v[i] = __expf(v[i] - m); s += v[i]; }
    #pragma unroll
    for (int off = 16; off > 0; off >>= 1)
        s += __shfl_xor_sync(0xffffffff, s, off);
    if ((t & 31) == 0) red[t >> 5] = s;
    __syncthreads();
    s = red[0] + red[1] + red[2] + red[3];
    float inv = 1.f/s;
    #pragma unroll
    for (int i = 0; i < 4; i++) row[t + i*128] = v[i]*inv;
}

// ---------------- launch ----------------
extern "C" void kernel_launch(void* const* d_in, const int* in_sizes, int n_in,
                              void* d_out, int out_size) {
    const float* data      = (const float*)d_in[0];
    const float* dist      = (const float*)d_in[1];
    const float* cur_dist  = (const float*)d_in[2];
    const float* capacity  = (const float*)d_in[3];
    const float* ninf_mask = (const float*)d_in[4];
    const float* log_scale = (const float*)d_in[5];
    const float* emb_W     = (const float*)d_in[6];
    const float* emb_b     = (const float*)d_in[7];
    const float* Wq        = (const float*)d_in[8];
    const float* Wk        = (const float*)d_in[9];
    const float* Wv        = (const float*)d_in[10];
    const float* aft_alpha = (const float*)d_in[11];
    const float* n1_w      = (const float*)d_in[12];
    const float* n1_b      = (const float*)d_in[13];
    const float* ff_W1     = (const float*)d_in[14];
    const float* ff_b1     = (const float*)d_in[15];
    const float* ff_W2     = (const float*)d_in[16];
    const float* ff_b2     = (const float*)d_in[17];
    const float* n2_w      = (const float*)d_in[18];
    const float* n2_b      = (const float*)d_in[19];
    const float* dWq       = (const float*)d_in[20];
    const float* dWk       = (const float*)d_in[21];
    const float* dWv       = (const float*)d_in[22];
    const float* dec_alpha = (const float*)d_in[23];
    const float* p_alpha   = (const float*)d_in[24];
    float* out = (float*)d_out;

    float *x, *y, *h, *sq, *ek, *ekv, *hid, *aft, *gq, *gm;
    cudaGetSymbolAddress((void**)&x,   g_x);
    cudaGetSymbolAddress((void**)&y,   g_y);
    cudaGetSymbolAddress((void**)&h,   g_h);
    cudaGetSymbolAddress((void**)&sq,  g_sq);
    cudaGetSymbolAddress((void**)&ek,  g_ek);
    cudaGetSymbolAddress((void**)&ekv, g_ekv);
    cudaGetSymbolAddress((void**)&hid, g_hid);
    cudaGetSymbolAddress((void**)&aft, g_aft);
    cudaGetSymbolAddress((void**)&gq,  g_gq);
    cudaGetSymbolAddress((void**)&gm,  g_gm);

    embed_kernel<<<M_TOT, EE>>>(data, emb_W, emb_b, x);

    for (int l = 0; l < LLAYERS; l++) {
        qkv_kernel<<<dim3(M_TOT/64, EE/64), 256>>>(
            x, Wq + (size_t)l*EE*EE, Wk + (size_t)l*EE*EE, Wv + (size_t)l*EE*EE,
            sq, ek, ekv);
        aft_enc_kernel<<<dim3(NN/64, 1, BB), 256>>>(
            dist, log_scale, aft_alpha, l, ekv, ek, x, sq, y);
        inorm_kernel<<<BB, dim3(128, 8)>>>(y, h, n1_w + l*EE, n1_b + l*EE);
        ff1_kernel<<<dim3(M_TOT/64, FFD/64), 256>>>(
            h, ff_W1 + (size_t)l*EE*FFD, ff_b1 + l*FFD, hid);
        ff2_kernel<<<dim3(M_TOT/64, EE/64), 256>>>(
            hid, ff_W2 + (size_t)l*FFD*EE, ff_b2 + l*EE, h, y);
        inorm_kernel<<<BB, dim3(128, 8)>>>(y, x, n2_w + l*EE, n2_b + l*EE);
    }

    // decoder
    deckv_kernel<<<dim3(M_TOT/64, EE/64), 256>>>(x, dWk, dWv, ek, ekv);
    gmean_kernel<<<BB, dim3(128, 8)>>>(x, gm);
    gq_kernel<<<BB, 128>>>(gm, dWq, gq);
    dec_aft_kernel<<<dim3(PP/64, 1, BB), 256>>>(
        cur_dist, ninf_mask, log_scale, dec_alpha, ekv, ek, gq, capacity, dWq, aft);
    score_kernel<<<dim3(PP/64, NN/64, BB), 256>>>(
        aft, x, cur_dist, ninf_mask, log_scale, p_alpha, out);
    softmax_kernel<<<BB*PP, 128>>>(out);
}

// round 7
// speedup vs baseline: 2.5972x; 2.5972x over previous
#include <cuda_runtime.h>
#include <math.h>

#define BB 64
#define PP 512
#define NN 512
#define EE 128
#define FFD 512
#define LLAYERS 6
#define M_TOT (BB*NN)
#define EPS 1e-5f
#define INV_SQRT_E 0.08838834764831845f  /* 1/sqrt(128) */

// ---------------- scratch (static device globals; no alloc allowed) ----------------
__device__ float g_x  [BB*NN*EE];
__device__ float g_y  [BB*NN*EE];
__device__ float g_h  [BB*NN*EE];
__device__ float g_sq [BB*NN*EE];
__device__ float g_ek [BB*NN*EE];
__device__ float g_ekv[BB*NN*EE];
__device__ float g_hid[BB*NN*FFD];
__device__ float g_aft[BB*PP*EE];
__device__ float g_gq [BB*EE];
__device__ float g_gm [BB*EE];

// ---------------- embedding ----------------
__global__ void embed_kernel(const float* __restrict__ data,
                             const float* __restrict__ W,
                             const float* __restrict__ bias,
                             float* __restrict__ X) {
    int idx = blockIdx.x;
    int e   = threadIdx.x;
    float d0 = data[idx*2+0], d1 = data[idx*2+1];
    X[(size_t)idx*EE + e] = d0*W[e] + d1*W[EE+e] + bias[e];
}

// =====================================================================
// qkv GEMM: BM=128, BN=64, BK=16, 256 thr, 8x4 microtile, 3 matrices
// =====================================================================
__global__ __launch_bounds__(256) void qkv_kernel(
        const float* __restrict__ X,
        const float* __restrict__ Wq,
        const float* __restrict__ Wk,
        const float* __restrict__ Wv,
        float* __restrict__ SQ,
        float* __restrict__ EK,
        float* __restrict__ EKV) {
    const int m0 = blockIdx.x*128, n0 = blockIdx.y*64;
    __shared__ float As[16][132];
    __shared__ float Bq[16][64], Bk[16][64], Bv[16][64];
    float aq[8][4] = {}, ak[8][4] = {}, av[8][4] = {};
    const int tid = threadIdx.x, tx = tid & 15, ty = tid >> 4;
    const int am = tid >> 2, ac4 = (tid & 3)*4;
    const int bk = tid >> 4, bn = (tid & 15)*4;

    for (int k0 = 0; k0 < EE; k0 += 16) {
        #pragma unroll
        for (int h = 0; h < 2; h++) {
            int m = am + h*64;
            float4 v = *(const float4*)&X[(size_t)(m0+m)*EE + k0 + ac4];
            As[ac4+0][m] = v.x; As[ac4+1][m] = v.y;
            As[ac4+2][m] = v.z; As[ac4+3][m] = v.w;
        }
        *(float4*)&Bq[bk][bn] = *(const float4*)&Wq[(size_t)(k0+bk)*EE + n0 + bn];
        *(float4*)&Bk[bk][bn] = *(const float4*)&Wk[(size_t)(k0+bk)*EE + n0 + bn];
        *(float4*)&Bv[bk][bn] = *(const float4*)&Wv[(size_t)(k0+bk)*EE + n0 + bn];
        __syncthreads();
        #pragma unroll
        for (int kk = 0; kk < 16; kk++) {
            float4 a0 = *(const float4*)&As[kk][ty*8];
            float4 a1 = *(const float4*)&As[kk][ty*8+4];
            float a[8] = {a0.x,a0.y,a0.z,a0.w,a1.x,a1.y,a1.z,a1.w};
            float4 q4 = *(const float4*)&Bq[kk][tx*4];
            float4 k4 = *(const float4*)&Bk[kk][tx*4];
            float4 v4 = *(const float4*)&Bv[kk][tx*4];
            float qb[4] = {q4.x,q4.y,q4.z,q4.w};
            float kb[4] = {k4.x,k4.y,k4.z,k4.w};
            float vb[4] = {v4.x,v4.y,v4.z,v4.w};
            #pragma unroll
            for (int i = 0; i < 8; i++)
                #pragma unroll
                for (int j = 0; j < 4; j++) {
                    aq[i][j] += a[i]*qb[j];
                    ak[i][j] += a[i]*kb[j];
                    av[i][j] += a[i]*vb[j];
                }
        }
        __syncthreads();
    }
    #pragma unroll
    for (int i = 0; i < 8; i++) {
        int row = m0 + ty*8 + i;
        size_t o = (size_t)row*EE + n0 + tx*4;
        float4 sqo, eko, evo;
        float* sp = &sqo.x; float* ep = &eko.x; float* vp = &evo.x;
        #pragma unroll
        for (int j = 0; j < 4; j++) {
            sp[j] = 1.f/(1.f + __expf(-aq[i][j]));
            float e = __expf(ak[i][j]);
            ep[j] = e;
            vp[j] = e*av[i][j];
        }
        *(float4*)&SQ[o]  = sqo;
        *(float4*)&EK[o]  = eko;
        *(float4*)&EKV[o] = evo;
    }
}

// =====================================================================
// dec k/v GEMM: same shape, 2 matrices
// =====================================================================
__global__ __launch_bounds__(256) void deckv_kernel(
        const float* __restrict__ X,
        const float* __restrict__ Wk,
        const float* __restrict__ Wv,
        float* __restrict__ EK,
        float* __restrict__ EKV) {
    const int m0 = blockIdx.x*128, n0 = blockIdx.y*64;
    __shared__ float As[16][132];
    __shared__ float Bk[16][64], Bv[16][64];
    float ak[8][4] = {}, av[8][4] = {};
    const int tid = threadIdx.x, tx = tid & 15, ty = tid >> 4;
    const int am = tid >> 2, ac4 = (tid & 3)*4;
    const int bk = tid >> 4, bn = (tid & 15)*4;

    for (int k0 = 0; k0 < EE; k0 += 16) {
        #pragma unroll
        for (int h = 0; h < 2; h++) {
            int m = am + h*64;
            float4 v = *(const float4*)&X[(size_t)(m0+m)*EE + k0 + ac4];
            As[ac4+0][m] = v.x; As[ac4+1][m] = v.y;
            As[ac4+2][m] = v.z; As[ac4+3][m] = v.w;
        }
        *(float4*)&Bk[bk][bn] = *(const float4*)&Wk[(size_t)(k0+bk)*EE + n0 + bn];
        *(float4*)&Bv[bk][bn] = *(const float4*)&Wv[(size_t)(k0+bk)*EE + n0 + bn];
        __syncthreads();
        #pragma unroll
        for (int kk = 0; kk < 16; kk++) {
            float4 a0 = *(const float4*)&As[kk][ty*8];
            float4 a1 = *(const float4*)&As[kk][ty*8+4];
            float a[8] = {a0.x,a0.y,a0.z,a0.w,a1.x,a1.y,a1.z,a1.w};
            float4 k4 = *(const float4*)&Bk[kk][tx*4];
            float4 v4 = *(const float4*)&Bv[kk][tx*4];
            float kb[4] = {k4.x,k4.y,k4.z,k4.w};
            float vb[4] = {v4.x,v4.y,v4.z,v4.w};
            #pragma unroll
            for (int i = 0; i < 8; i++)
                #pragma unroll
                for (int j = 0; j < 4; j++) {
                    ak[i][j] += a[i]*kb[j];
                    av[i][j] += a[i]*vb[j];
                }
        }
        __syncthreads();
    }
    #pragma unroll
    for (int i = 0; i < 8; i++) {
        int row = m0 + ty*8 + i;
        size_t o = (size_t)row*EE + n0 + tx*4;
        float4 eko, evo;
        float* ep = &eko.x; float* vp = &evo.x;
        #pragma unroll
        for (int j = 0; j < 4; j++) {
            float e = __expf(ak[i][j]);
            ep[j] = e;
            vp[j] = e*av[i][j];
        }
        *(float4*)&EK[o]  = eko;
        *(float4*)&EKV[o] = evo;
    }
}

// =====================================================================
// encoder AFT: BM=128, BN=64, BK=16, K=512, dual GEMM, A=exp(s*dist) on the fly
// =====================================================================
__global__ __launch_bounds__(256) void aft_enc_kernel(
        const float* __restrict__ dist,
        const float* __restrict__ ls,
        const float* __restrict__ alpha, int l,
        const float* __restrict__ EKV,
        const float* __restrict__ EK,
        const float* __restrict__ X,
        const float* __restrict__ SQ,
        float* __restrict__ Y) {
    const int b = blockIdx.z;
    const int m0 = blockIdx.x*128, n0 = blockIdx.y*64;
    const float s = ls[0]*alpha[l];
    const float* D  = dist + (size_t)b*NN*NN;
    const float* B1 = EKV  + (size_t)b*NN*EE;
    const float* B2 = EK   + (size_t)b*NN*EE;
    __shared__ float As[16][132];
    __shared__ float Bs1[16][64], Bs2[16][64];
    float a1[8][4] = {}, a2[8][4] = {};
    const int tid = threadIdx.x, tx = tid & 15, ty = tid >> 4;
    const int am = tid >> 2, ac4 = (tid & 3)*4;
    const int bk = tid >> 4, bn = (tid & 15)*4;

    for (int k0 = 0; k0 < NN; k0 += 16) {
        #pragma unroll
        for (int h = 0; h < 2; h++) {
            int m = am + h*64;
            float4 v = *(const float4*)&D[(size_t)(m0+m)*NN + k0 + ac4];
            As[ac4+0][m] = __expf(s*v.x); As[ac4+1][m] = __expf(s*v.y);
            As[ac4+2][m] = __expf(s*v.z); As[ac4+3][m] = __expf(s*v.w);
        }
        *(float4*)&Bs1[bk][bn] = *(const float4*)&B1[(size_t)(k0+bk)*EE + n0 + bn];
        *(float4*)&Bs2[bk][bn] = *(const float4*)&B2[(size_t)(k0+bk)*EE + n0 + bn];
        __syncthreads();
        #pragma unroll
        for (int kk = 0; kk < 16; kk++) {
            float4 a0 = *(const float4*)&As[kk][ty*8];
            float4 a1f = *(const float4*)&As[kk][ty*8+4];
            float a[8] = {a0.x,a0.y,a0.z,a0.w,a1f.x,a1f.y,a1f.z,a1f.w};
            float4 p4 = *(const float4*)&Bs1[kk][tx*4];
            float4 q4 = *(const float4*)&Bs2[kk][tx*4];
            float pb[4] = {p4.x,p4.y,p4.z,p4.w};
            float qb[4] = {q4.x,q4.y,q4.z,q4.w};
            #pragma unroll
            for (int i = 0; i < 8; i++)
                #pragma unroll
                for (int j = 0; j < 4; j++) {
                    a1[i][j] += a[i]*pb[j];
                    a2[i][j] += a[i]*qb[j];
                }
        }
        __syncthreads();
    }
    #pragma unroll
    for (int i = 0; i < 8; i++) {
        int row = m0 + ty*8 + i;
        size_t base = ((size_t)b*NN + row)*EE + n0 + tx*4;
        float4 xv = *(const float4*)&X[base];
        float4 sv = *(const float4*)&SQ[base];
        float4 ov;
        ov.x = xv.x + sv.x*(a1[i][0]/a2[i][0]);
        ov.y = xv.y + sv.y*(a1[i][1]/a2[i][1]);
        ov.z = xv.z + sv.z*(a1[i][2]/a2[i][2]);
        ov.w = xv.w + sv.w*(a1[i][3]/a2[i][3]);
        *(float4*)&Y[base] = ov;
    }
}

// =====================================================================
// decoder AFT: BM=128(P), BN=64, K=512, A=exp(s*cd+ninf)
// =====================================================================
__global__ __launch_bounds__(256) void dec_aft_kernel(
        const float* __restrict__ cur_dist,
        const float* __restrict__ ninf,
        const float* __restrict__ ls,
        const float* __restrict__ dalpha,
        const float* __restrict__ EKV,
        const float* __restrict__ EK,
        const float* __restrict__ GQ,
        const float* __restrict__ cap,
        const float* __restrict__ dWq,
        float* __restrict__ AFT) {
    const int b = blockIdx.z;
    const int m0 = blockIdx.x*128, n0 = blockIdx.y*64;
    const float s = ls[0]*dalpha[0];
    const float* CD = cur_dist + (size_t)b*PP*NN;
    const float* NM = ninf     + (size_t)b*PP*NN;
    const float* B1 = EKV + (size_t)b*NN*EE;
    const float* B2 = EK  + (size_t)b*NN*EE;
    __shared__ float As[16][132];
    __shared__ float Bs1[16][64], Bs2[16][64];
    float a1[8][4] = {}, a2[8][4] = {};
    const int tid = threadIdx.x, tx = tid & 15, ty = tid >> 4;
    const int am = tid >> 2, ac4 = (tid & 3)*4;
    const int bk = tid >> 4, bn = (tid & 15)*4;

    for (int k0 = 0; k0 < NN; k0 += 16) {
        #pragma unroll
        for (int h = 0; h < 2; h++) {
            int m = am + h*64;
            size_t off = (size_t)(m0+m)*NN + k0 + ac4;
            float4 cv = *(const float4*)&CD[off];
            float4 nv = *(const float4*)&NM[off];
            As[ac4+0][m] = __expf(s*cv.x + nv.x);
            As[ac4+1][m] = __expf(s*cv.y + nv.y);
            As[ac4+2][m] = __expf(s*cv.z + nv.z);
            As[ac4+3][m] = __expf(s*cv.w + nv.w);
        }
        *(float4*)&Bs1[bk][bn] = *(const float4*)&B1[(size_t)(k0+bk)*EE + n0 + bn];
        *(float4*)&Bs2[bk][bn] = *(const float4*)&B2[(size_t)(k0+bk)*EE + n0 + bn];
        __syncthreads();
        #pragma unroll
        for (int kk = 0; kk < 16; kk++) {
            float4 a0 = *(const float4*)&As[kk][ty*8];
            float4 a1f = *(const float4*)&As[kk][ty*8+4];
            float a[8] = {a0.x,a0.y,a0.z,a0.w,a1f.x,a1f.y,a1f.z,a1f.w};
            float4 p4 = *(const float4*)&Bs1[kk][tx*4];
            float4 q4 = *(const float4*)&Bs2[kk][tx*4];
            float pb[4] = {p4.x,p4.y,p4.z,p4.w};
            float qb[4] = {q4.x,q4.y,q4.z,q4.w};
            #pragma unroll
            for (int i = 0; i < 8; i++)
                #pragma unroll
                for (int j = 0; j < 4; j++) {
                    a1[i][j] += a[i]*pb[j];
                    a2[i][j] += a[i]*qb[j];
                }
        }
        __syncthreads();
    }
    // epilogue: cols shared across the 8 rows
    float4 g4 = *(const float4*)&GQ[b*EE + n0 + tx*4];
    float4 w4 = *(const float4*)&dWq[EE*EE + n0 + tx*4];
    float gq4[4] = {g4.x,g4.y,g4.z,g4.w};
    float wq4[4] = {w4.x,w4.y,w4.z,w4.w};
    #pragma unroll
    for (int i = 0; i < 8; i++) {
        int p = m0 + ty*8 + i;
        float cv = cap[(size_t)b*PP + p];
        float4 ov; float* op = &ov.x;
        #pragma unroll
        for (int j = 0; j < 4; j++) {
            float qv = gq4[j] + cv*wq4[j];
            float sg = 1.f/(1.f + __expf(-qv));
            op[j] = sg*(a1[i][j]/a2[i][j]);
        }
        *(float4*)&AFT[((size_t)b*PP + p)*EE + n0 + tx*4] = ov;
    }
}

// =====================================================================
// FF1: hid = relu(h@W1 + b1); BM=128, BN=128, BK=16, 8x8 microtile
// =====================================================================
__global__ __launch_bounds__(256) void ff1_kernel(
        const float* __restrict__ H,
        const float* __restrict__ W1,
        const float* __restrict__ b1,
        float* __restrict__ HID) {
    const int m0 = blockIdx.x*128, n0 = blockIdx.y*128;
    __shared__ float As[16][132];
    __shared__ float Bs[16][128];
    float acc[8][8] = {};
    const int tid = threadIdx.x, tx = tid & 15, ty = tid >> 4;
    const int am = tid >> 2, ac4 = (tid & 3)*4;
    const int bk = tid >> 4, bn = (tid & 15)*8;

    for (int k0 = 0; k0 < EE; k0 += 16) {
        #pragma unroll
        for (int h = 0; h < 2; h++) {
            int m = am + h*64;
            float4 v = *(const float4*)&H[(size_t)(m0+m)*EE + k0 + ac4];
            As[ac4+0][m] = v.x; As[ac4+1][m] = v.y;
            As[ac4+2][m] = v.z; As[ac4+3][m] = v.w;
        }
        *(float4*)&Bs[bk][bn]   = *(const float4*)&W1[(size_t)(k0+bk)*FFD + n0 + bn];
        *(float4*)&Bs[bk][bn+4] = *(const float4*)&W1[(size_t)(k0+bk)*FFD + n0 + bn + 4];
        __syncthreads();
        #pragma unroll
        for (int kk = 0; kk < 16; kk++) {
            float4 a0 = *(const float4*)&As[kk][ty*8];
            float4 a1 = *(const float4*)&As[kk][ty*8+4];
            float a[8] = {a0.x,a0.y,a0.z,a0.w,a1.x,a1.y,a1.z,a1.w};
            float4 b0 = *(const float4*)&Bs[kk][tx*8];
            float4 b1v = *(const float4*)&Bs[kk][tx*8+4];
            float bb[8] = {b0.x,b0.y,b0.z,b0.w,b1v.x,b1v.y,b1v.z,b1v.w};
            #pragma unroll
            for (int i = 0; i < 8; i++)
                #pragma unroll
                for (int j = 0; j < 8; j++)
                    acc[i][j] += a[i]*bb[j];
        }
        __syncthreads();
    }
    float4 bb0 = *(const float4*)&b1[n0 + tx*8];
    float4 bb1 = *(const float4*)&b1[n0 + tx*8 + 4];
    float bias[8] = {bb0.x,bb0.y,bb0.z,bb0.w,bb1.x,bb1.y,bb1.z,bb1.w};
    #pragma unroll
    for (int i = 0; i < 8; i++) {
        int row = m0 + ty*8 + i;
        size_t o = (size_t)row*FFD + n0 + tx*8;
        float4 o0, o1; float* p0 = &o0.x; float* p1 = &o1.x;
        #pragma unroll
        for (int j = 0; j < 4; j++) {
            p0[j] = fmaxf(acc[i][j]   + bias[j],   0.f);
            p1[j] = fmaxf(acc[i][j+4] + bias[j+4], 0.f);
        }
        *(float4*)&HID[o]   = o0;
        *(float4*)&HID[o+4] = o1;
    }
}

// =====================================================================
// FF2: y = h + hid@W2 + b2; BM=128, BN=128(=E), BK=16, K=512
// =====================================================================
__global__ __launch_bounds__(256) void ff2_kernel(
        const float* __restrict__ HID,
        const float* __restrict__ W2,
        const float* __restrict__ b2,
        const float* __restrict__ H,
        float* __restrict__ Y) {
    const int m0 = blockIdx.x*128;
    __shared__ float As[16][132];
    __shared__ float Bs[16][128];
    float acc[8][8] = {};
    const int tid = threadIdx.x, tx = tid & 15, ty = tid >> 4;
    const int am = tid >> 2, ac4 = (tid & 3)*4;
    const int bk = tid >> 4, bn = (tid & 15)*8;

    for (int k0 = 0; k0 < FFD; k0 += 16) {
        #pragma unroll
        for (int h = 0; h < 2; h++) {
            int m = am + h*64;
            float4 v = *(const float4*)&HID[(size_t)(m0+m)*FFD + k0 + ac4];
            As[ac4+0][m] = v.x; As[ac4+1][m] = v.y;
            As[ac4+2][m] = v.z; As[ac4+3][m] = v.w;
        }
        *(float4*)&Bs[bk][bn]   = *(const float4*)&W2[(size_t)(k0+bk)*EE + bn];
        *(float4*)&Bs[bk][bn+4] = *(const float4*)&W2[(size_t)(k0+bk)*EE + bn + 4];
        __syncthreads();
        #pragma unroll
        for (int kk = 0; kk < 16; kk++) {
            float4 a0 = *(const float4*)&As[kk][ty*8];
            float4 a1 = *(const float4*)&As[kk][ty*8+4];
            float a[8] = {a0.x,a0.y,a0.z,a0.w,a1.x,a1.y,a1.z,a1.w};
            float4 b0 = *(const float4*)&Bs[kk][tx*8];
            float4 b1v = *(const float4*)&Bs[kk][tx*8+4];
            float bb[8] = {b0.x,b0.y,b0.z,b0.w,b1v.x,b1v.y,b1v.z,b1v.w};
            #pragma unroll
            for (int i = 0; i < 8; i++)
                #pragma unroll
                for (int j = 0; j < 8; j++)
                    acc[i][j] += a[i]*bb[j];
        }
        __syncthreads();
    }
    float4 bb0 = *(const float4*)&b2[tx*8];
    float4 bb1 = *(const float4*)&b2[tx*8 + 4];
    float bias[8] = {bb0.x,bb0.y,bb0.z,bb0.w,bb1.x,bb1.y,bb1.z,bb1.w};
    #pragma unroll
    for (int i = 0; i < 8; i++) {
        int row = m0 + ty*8 + i;
        size_t o = (size_t)row*EE + tx*8;
        float4 h0 = *(const float4*)&H[o];
        float4 h1 = *(const float4*)&H[o+4];
        float4 o0, o1;
        o0.x = h0.x + acc[i][0] + bias[0];
        o0.y = h0.y + acc[i][1] + bias[1];
        o0.z = h0.z + acc[i][2] + bias[2];
        o0.w = h0.w + acc[i][3] + bias[3];
        o1.x = h1.x + acc[i][4] + bias[4];
        o1.y = h1.y + acc[i][5] + bias[5];
        o1.z = h1.z + acc[i][6] + bias[6];
        o1.w = h1.w + acc[i][7] + bias[7];
        *(float4*)&Y[o]   = o0;
        *(float4*)&Y[o+4] = o1;
    }
}

// ---------------- instance norm over node dim (axis=1) ----------------
__global__ void inorm_kernel(const float* __restrict__ src,
                             float* __restrict__ dst,
                             const float* __restrict__ w,
                             const float* __restrict__ bias) {
    int b = blockIdx.x;
    int e = threadIdx.x;
    int c = threadIdx.y;
    const float* S = src + (size_t)b*NN*EE;
    float s = 0.f, s2 = 0.f;
    for (int n = c*64; n < c*64 + 64; n++) {
        float v = S[(size_t)n*EE + e];
        s += v; s2 += v*v;
    }
    __shared__ float ssum[8][128], ssq[8][128];
    __shared__ float smu[128], srs[128];
    ssum[c][e] = s; ssq[c][e] = s2;
    __syncthreads();
    if (c == 0) {
        float ts = 0.f, t2 = 0.f;
        #pragma unroll
        for (int i = 0; i < 8; i++) { ts += ssum[i][e]; t2 += ssq[i][e]; }
        float mu = ts*(1.f/NN);
        float var = t2*(1.f/NN) - mu*mu;
        smu[e] = mu;
        srs[e] = rsqrtf(var + EPS);
    }
    __syncthreads();
    float mu = smu[e], rs = srs[e], ww = w[e], bb = bias[e];
    float* Dd = dst + (size_t)b*NN*EE;
    for (int n = c*64; n < c*64 + 64; n++) {
        size_t o = (size_t)n*EE + e;
        Dd[o] = (S[o] - mu)*rs*ww + bb;
    }
}

// ---------------- graph mean over nodes ----------------
__global__ void gmean_kernel(const float* __restrict__ X, float* __restrict__ GM) {
    int b = blockIdx.x, e = threadIdx.x, c = threadIdx.y;
    float s = 0.f;
    for (int n = c*64; n < c*64 + 64; n++)
        s += X[((size_t)b*NN + n)*EE + e];
    __shared__ float sm[8][128];
    sm[c][e] = s;
    __syncthreads();
    if (c == 0) {
        float t = 0.f;
        #pragma unroll
        for (int i = 0; i < 8; i++) t += sm[i][e];
        GM[b*EE + e] = t*(1.f/NN);
    }
}

// ---------------- gq = gmean @ dWq[0:E,:] ----------------
__global__ void gq_kernel(const float* __restrict__ GM,
                          const float* __restrict__ dWq,
                          float* __restrict__ GQ) {
    int b = blockIdx.x, e = threadIdx.x;
    float acc = 0.f;
    for (int i = 0; i < EE; i++)
        acc += GM[b*EE + i]*dWq[i*EE + e];
    GQ[b*EE + e] = acc;
}

// =====================================================================
// score GEMM: S = aft @ enc^T (NT); BM=128(P), BN=128(N), BK=16, K=128
// =====================================================================
__global__ __launch_bounds__(256) void score_kernel(
        const float* __restrict__ AFT,
        const float* __restrict__ ENC,
        const float* __restrict__ cur_dist,
        const float* __restrict__ ninf,
        const float* __restrict__ ls,
        const float* __restrict__ palpha,
        float* __restrict__ OUT) {
    const int b = blockIdx.z;
    const int p0 = blockIdx.x*128, n0 = blockIdx.y*128;
    const float ps = ls[0]*palpha[0];
    const float* A  = AFT + (size_t)b*PP*EE;
    const float* Eb = ENC + (size_t)b*NN*EE;
    __shared__ float As[16][132];
    __shared__ float Bs[16][132];
    float acc[8][8] = {};
    const int tid = threadIdx.x, tx = tid & 15, ty = tid >> 4;
    const int am = tid >> 2, ac4 = (tid & 3)*4;

    for (int k0 = 0; k0 < EE; k0 += 16) {
        #pragma unroll
        for (int h = 0; h < 2; h++) {
            int m = am + h*64;
            float4 v = *(const float4*)&A[(size_t)(p0+m)*EE + k0 + ac4];
            As[ac4+0][m] = v.x; As[ac4+1][m] = v.y;
            As[ac4+2][m] = v.z; As[ac4+3][m] = v.w;
        }
        // B transposed: Bs[k][n] from Eb[n][k]
        #pragma unroll
        for (int it = 0; it < 2; it++) {
            int idx = tid + it*256;
            int n = idx >> 2, c4 = (idx & 3)*4;
            float4 v = *(const float4*)&Eb[(size_t)(n0+n)*EE + k0 + c4];
            Bs[c4+0][n] = v.x; Bs[c4+1][n] = v.y;
            Bs[c4+2][n] = v.z; Bs[c4+3][n] = v.w;
        }
        __syncthreads();
        #pragma unroll
        for (int kk = 0; kk < 16; kk++) {
            float4 a0 = *(const float4*)&As[kk][ty*8];
            float4 a1 = *(const float4*)&As[kk][ty*8+4];
            float a[8] = {a0.x,a0.y,a0.z,a0.w,a1.x,a1.y,a1.z,a1.w};
            float4 b0 = *(const float4*)&Bs[kk][tx*8];
            float4 b1v = *(const float4*)&Bs[kk][tx*8+4];
            float bb[8] = {b0.x,b0.y,b0.z,b0.w,b1v.x,b1v.y,b1v.z,b1v.w};
            #pragma unroll
            for (int i = 0; i < 8; i++)
                #pragma unroll
                for (int j = 0; j < 8; j++)
                    acc[i][j] += a[i]*bb[j];
        }
        __syncthreads();
    }
    #pragma unroll
    for (int i = 0; i < 8; i++) {
        int p = p0 + ty*8 + i;
        size_t o = ((size_t)b*PP + p)*NN + n0 + tx*8;
        float4 c0 = *(const float4*)&cur_dist[o];
        float4 c1 = *(const float4*)&cur_dist[o+4];
        float4 m0v = *(const float4*)&ninf[o];
        float4 m1v = *(const float4*)&ninf[o+4];
        float cd[8] = {c0.x,c0.y,c0.z,c0.w,c1.x,c1.y,c1.z,c1.w};
        float nm[8] = {m0v.x,m0v.y,m0v.z,m0v.w,m1v.x,m1v.y,m1v.z,m1v.w};
        float4 o0, o1; float* p0p = &o0.x; float* p1p = &o1.x;
        #pragma unroll
        for (int j = 0; j < 8; j++) {
            float sc = acc[i][j]*INV_SQRT_E + ps*cd[j];
            float r = 10.f*tanhf(sc) + nm[j];
            if (j < 4) p0p[j] = r; else p1p[j-4] = r;
        }
        *(float4*)&OUT[o]   = o0;
        *(float4*)&OUT[o+4] = o1;
    }
}

// ---------------- row softmax over last dim (512) ----------------
__global__ void softmax_kernel(float* __restrict__ OUT) {
    float* row = OUT + (size_t)blockIdx.x*NN;
    int t = threadIdx.x;
    float v[4];
    #pragma unroll
    for (int i = 0; i < 4; i++) v[i] = row[t + i*128];
    float m = fmaxf(fmaxf(v[0], v[1]), fmaxf(v[2], v[3]));
    __shared__ float red[4];
    #pragma unroll
    for (int off = 16; off > 0; off >>= 1)
        m = fmaxf(m, __shfl_xor_sync(0xffffffff, m, off));
    if ((t & 31) == 0) red[t >> 5] = m;
    __syncthreads();
    m = fmaxf(fmaxf(red[0], red[1]), fmaxf(red[2], red[3]));
    __syncthreads();
    float s = 0.f;
    #pragma unroll
    for (int i = 0; i < 4; i++) { v[i] = __expf(v[i] - m); s += v[i]; }
    #pragma unroll
    for (int off = 16; off > 0; off >>= 1)
        s += __shfl_xor_sync(0xffffffff, s, off);
    if ((t & 31) == 0) red[t >> 5] = s;
    __syncthreads();
    s = red[0] + red[1] + red[2] + red[3];
    float inv = 1.f/s;
    #pragma unroll
    for (int i = 0; i < 4; i++) row[t + i*128] = v[i]*inv;
}

// ---------------- launch ----------------
extern "C" void kernel_launch(void* const* d_in, const int* in_sizes, int n_in,
                              void* d_out, int out_size) {
    const float* data      = (const float*)d_in[0];
    const float* dist      = (const float*)d_in[1];
    const float* cur_dist  = (const float*)d_in[2];
    const float* capacity  = (const float*)d_in[3];
    const float* ninf_mask = (const float*)d_in[4];
    const float* log_scale = (const float*)d_in[5];
    const float* emb_W     = (const float*)d_in[6];
    const float* emb_b     = (const float*)d_in[7];
    const float* Wq        = (const float*)d_in[8];
    const float* Wk        = (const float*)d_in[9];
    const float* Wv        = (const float*)d_in[10];
    const float* aft_alpha = (const float*)d_in[11];
    const float* n1_w      = (const float*)d_in[12];
    const float* n1_b      = (const float*)d_in[13];
    const float* ff_W1     = (const float*)d_in[14];
    const float* ff_b1     = (const float*)d_in[15];
    const float* ff_W2     = (const float*)d_in[16];
    const float* ff_b2     = (const float*)d_in[17];
    const float* n2_w      = (const float*)d_in[18];
    const float* n2_b      = (const float*)d_in[19];
    const float* dWq       = (const float*)d_in[20];
    const float* dWk       = (const float*)d_in[21];
    const float* dWv       = (const float*)d_in[22];
    const float* dec_alpha = (const float*)d_in[23];
    const float* p_alpha   = (const float*)d_in[24];
    float* out = (float*)d_out;

    float *x, *y, *h, *sq, *ek, *ekv, *hid, *aft, *gq, *gm;
    cudaGetSymbolAddress((void**)&x,   g_x);
    cudaGetSymbolAddress((void**)&y,   g_y);
    cudaGetSymbolAddress((void**)&h,   g_h);
    cudaGetSymbolAddress((void**)&sq,  g_sq);
    cudaGetSymbolAddress((void**)&ek,  g_ek);
    cudaGetSymbolAddress((void**)&ekv, g_ekv);
    cudaGetSymbolAddress((void**)&hid, g_hid);
    cudaGetSymbolAddress((void**)&aft, g_aft);
    cudaGetSymbolAddress((void**)&gq,  g_gq);
    cudaGetSymbolAddress((void**)&gm,  g_gm);

    embed_kernel<<<M_TOT, EE>>>(data, emb_W, emb_b, x);

    for (int l = 0; l < LLAYERS; l++) {
        qkv_kernel<<<dim3(M_TOT/128, 2), 256>>>(
            x, Wq + (size_t)l*EE*EE, Wk + (size_t)l*EE*EE, Wv + (size_t)l*EE*EE,
            sq, ek, ekv);
        aft_enc_kernel<<<dim3(NN/128, 2, BB), 256>>>(
            dist, log_scale, aft_alpha, l, ekv, ek, x, sq, y);
        inorm_kernel<<<BB, dim3(128, 8)>>>(y, h, n1_w + l*EE, n1_b + l*EE);
        ff1_kernel<<<dim3(M_TOT/128, FFD/128), 256>>>(
            h, ff_W1 + (size_t)l*EE*FFD, ff_b1 + l*FFD, hid);
        ff2_kernel<<<dim3(M_TOT/128, 1), 256>>>(
            hid, ff_W2 + (size_t)l*FFD*EE, ff_b2 + l*EE, h, y);
        inorm_kernel<<<BB, dim3(128, 8)>>>(y, x, n2_w + l*EE, n2_b + l*EE);
    }

    // decoder
    deckv_kernel<<<dim3(M_TOT/128, 2), 256>>>(x, dWk, dWv, ek, ekv);
    gmean_kernel<<<BB, dim3(128, 8)>>>(x, gm);
    gq_kernel<<<BB, 128>>>(gm, dWq, gq);
    dec_aft_kernel<<<dim3(PP/128, 2, BB), 256>>>(
        cur_dist, ninf_mask, log_scale, dec_alpha, ekv, ek, gq, capacity, dWq, aft);
    score_kernel<<<dim3(PP/128, NN/128, BB), 256>>>(
        aft, x, cur_dist, ninf_mask, log_scale, p_alpha, out);
    softmax_kernel<<<BB*PP, 128>>>(out);
}